// round 16
// baseline (speedup 1.0000x reference)
#include <cuda_runtime.h>
#include <cuda_fp16.h>
#include <cstdint>

#define IN_F   4096
#define OUT_F  4096
#define M_TOK  8192
#define XK     256                      // stage-1 contraction (x_flat cols)
#define K2     512                      // stage-2 contraction = 16*32
#define YPITCH ((size_t)M_TOK * K2)     // per-p Y matrix elems
#define VPITCH ((size_t)1024 * K2)      // per-p V matrix elems

// Scratch (allocation-free rule: __device__ globals).
__device__ __align__(256) __half g_wd[128 * 256];
__device__ __align__(256) __half g_y[4 * YPITCH];
__device__ __align__(256) __half g_v[4 * VPITCH];
__device__ float g_xs[M_TOK];
__device__ float g_xb[M_TOK * 4];

// ---------------------------------------------------------------------------
// helpers
// ---------------------------------------------------------------------------
__device__ __forceinline__ void mma_f16(float* c, const uint32_t* a, const uint32_t* b) {
    asm volatile(
        "mma.sync.aligned.m16n8k16.row.col.f32.f16.f16.f32 "
        "{%0,%1,%2,%3}, {%4,%5,%6,%7}, {%8,%9}, {%0,%1,%2,%3};\n"
        : "+f"(c[0]), "+f"(c[1]), "+f"(c[2]), "+f"(c[3])
        : "r"(a[0]), "r"(a[1]), "r"(a[2]), "r"(a[3]), "r"(b[0]), "r"(b[1]));
}
__device__ __forceinline__ void ldsm_x4(uint32_t* r, uint32_t addr) {
    asm volatile("ldmatrix.sync.aligned.m8n8.x4.shared.b16 {%0,%1,%2,%3}, [%4];\n"
                 : "=r"(r[0]), "=r"(r[1]), "=r"(r[2]), "=r"(r[3]) : "r"(addr));
}
__device__ __forceinline__ void cp16(uint32_t saddr, const void* g) {
    asm volatile("cp.async.cg.shared.global [%0], [%1], 16;\n" :: "r"(saddr), "l"(g) : "memory");
}
__device__ __forceinline__ void cp_commit() { asm volatile("cp.async.commit_group;\n" ::: "memory"); }
__device__ __forceinline__ void cp_wait1()  { asm volatile("cp.async.wait_group 1;\n" ::: "memory"); }
__device__ __forceinline__ void cp_wait0()  { asm volatile("cp.async.wait_group 0;\n" ::: "memory"); }

// swizzle for 32-col tiles: 2 rows per 128B line. r:0..127, c:0..31 (fp16)
__device__ __forceinline__ uint32_t swz32(int r, int c) {
    int line = r >> 1;
    int q = ((r & 1) << 2) | (c >> 3);
    return (uint32_t)((line << 7) | ((q ^ (line & 7)) << 4) | ((c & 7) << 1));
}
// swizzle for 64-col tiles: 1 row per 128B line. r: any, c:0..63 (fp16)
__device__ __forceinline__ uint32_t swz64(int r, int c) {
    int q = c >> 3;
    return (uint32_t)((r << 7) | (((q ^ (r & 7)) & 7) << 4) | ((c & 7) << 1));
}

// ---------------------------------------------------------------------------
// prep_wd: the only y_gemm dependency (tiny, runs first)
// ---------------------------------------------------------------------------
__global__ void prep_wd(const float* __restrict__ w_dec) {
    int i = blockIdx.x * 256 + threadIdx.x;        // < 32768
    g_wd[i] = __float2half_rn(w_dec[i]);
}

// ---------------------------------------------------------------------------
// MEGA kernel: blocks [0,1024): y_gemm (stage-1 GEMM, critical path);
//              blocks [1024,9216): V build;  blocks [9216,17408): aux x-scan.
// Light blocks overlap y_gemm's tail waves (pure DRAM vs tensor).
// ---------------------------------------------------------------------------
#define S1_OFF_B 8192
#define S1_STAGE 16384
#define S1_DYN   (3 * S1_STAGE + 128)

__global__ __launch_bounds__(256, 2)
void y_gemm_fused(const float* __restrict__ x,
                  const float* __restrict__ vq,
                  const float* __restrict__ d_std,
                  const float* __restrict__ b_dec) {
    if (blockIdx.x >= 1024) {
        if (blockIdx.x < 9216) {
            // ---- V build ----
            int i = (int)(blockIdx.x - 1024) * 256 + threadIdx.x;  // < 2097152
            int n = i >> 7, low = i & 127;
            int p = low >> 5, l = low & 31;
            int r = n >> 4, s = n & 15;
            float v = vq[i] * (d_std[p] + 1e-6f);
            g_v[(size_t)p * VPITCH + (size_t)r * K2 + s * 32 + l] = __float2half_rn(v);
        } else {
            // ---- aux: one block per token ----
            __shared__ float sh[8][5];
            const int t = blockIdx.x - 9216, c = threadIdx.x;
            const int lane = c & 31, w = c >> 5;
            const float* xr = x + (size_t)t * IN_F;
            float xc = 0.f;
#pragma unroll
            for (int s = 0; s < 16; ++s) xc += xr[s * 256 + c];
            float v[5];
            v[0] = xc;
            v[1] = xc * b_dec[c];
            v[2] = xc * b_dec[256 + c];
            v[3] = xc * b_dec[512 + c];
            v[4] = xc * b_dec[768 + c];
#pragma unroll
            for (int o = 16; o > 0; o >>= 1)
#pragma unroll
                for (int j = 0; j < 5; ++j)
                    v[j] += __shfl_xor_sync(0xffffffffu, v[j], o);
            if (lane == 0)
#pragma unroll
                for (int j = 0; j < 5; ++j) sh[w][j] = v[j];
            __syncthreads();
            if (w == 0 && lane < 8) {
                float a0 = sh[lane][0], a1 = sh[lane][1], a2 = sh[lane][2],
                      a3 = sh[lane][3], a4 = sh[lane][4];
#pragma unroll
                for (int o = 4; o > 0; o >>= 1) {
                    a0 += __shfl_xor_sync(0xffu, a0, o);
                    a1 += __shfl_xor_sync(0xffu, a1, o);
                    a2 += __shfl_xor_sync(0xffu, a2, o);
                    a3 += __shfl_xor_sync(0xffu, a3, o);
                    a4 += __shfl_xor_sync(0xffu, a4, o);
                }
                if (lane == 0) {
                    g_xs[t] = a0;
                    g_xb[t * 4 + 0] = a1; g_xb[t * 4 + 1] = a2;
                    g_xb[t * 4 + 2] = a3; g_xb[t * 4 + 3] = a4;
                }
            }
        }
        return;
    }

    // ---- y_gemm body (R7/R10 version, measured 46.4us) ----
    extern __shared__ __half smraw[];
    const uint32_t sdata = ((uint32_t)__cvta_generic_to_shared(smraw) + 127u) & ~127u;

    const int tid  = threadIdx.x;
    const int lane = tid & 31;
    const int warp = tid >> 5;
    const int wm   = warp >> 2;
    const int wn   = warp & 3;
    const int m0   = blockIdx.x * 128;

    const int u0 = tid, u1 = tid + 256;
    const int r0 = u0 >> 2, c0 = (u0 & 3) << 3;
    const int r1 = u1 >> 2, c1 = (u1 & 3) << 3;
    const uint32_t d0 = swz32(r0, c0), d1 = swz32(r1, c1);

    float acc[4][4][4] = {};
    float4 ra[2][2];

    auto loadA = [&](int kt) {
        const float4* p0 = reinterpret_cast<const float4*>(x + (size_t)(m0 + r0) * XK + kt * 32 + c0);
        const float4* p1 = reinterpret_cast<const float4*>(x + (size_t)(m0 + r1) * XK + kt * 32 + c1);
        ra[0][0] = p0[0]; ra[0][1] = p0[1];
        ra[1][0] = p1[0]; ra[1][1] = p1[1];
    };
    auto stsA = [&](uint32_t st) {
#pragma unroll
        for (int e = 0; e < 2; ++e) {
            const float* f = reinterpret_cast<const float*>(ra[e]);
            __half2 hv[4];
#pragma unroll
            for (int j = 0; j < 4; ++j)
                hv[j] = __halves2half2(__float2half_rn(f[2 * j]), __float2half_rn(f[2 * j + 1]));
            asm volatile("st.shared.v4.b32 [%0], {%1,%2,%3,%4};\n" ::
                "r"(st + (e ? d1 : d0)),
                "r"(*reinterpret_cast<uint32_t*>(&hv[0])), "r"(*reinterpret_cast<uint32_t*>(&hv[1])),
                "r"(*reinterpret_cast<uint32_t*>(&hv[2])), "r"(*reinterpret_cast<uint32_t*>(&hv[3])));
        }
    };
    auto cpB = [&](uint32_t st, int kt) {
        cp16(st + S1_OFF_B + d0, g_wd + r0 * 256 + kt * 32 + c0);
        cp16(st + S1_OFF_B + d1, g_wd + r1 * 256 + kt * 32 + c1);
        cp_commit();
    };
    auto stg = [&](int s) -> uint32_t { return sdata + (uint32_t)s * S1_STAGE; };

    // prologue
    loadA(0); stsA(stg(0)); cpB(stg(0), 0);
    loadA(1); stsA(stg(1)); cpB(stg(1), 1);
    loadA(2);

    int cur = 0;
    for (int kt = 0; kt < 8; ++kt) {
        if (kt < 7) cp_wait1(); else cp_wait0();
        __syncthreads();
        int nx = cur + 2; if (nx >= 3) nx -= 3;
        if (kt + 2 < 8) cpB(stg(nx), kt + 2);   // cheap prefetch before MMAs

#pragma unroll
        for (int ks = 0; ks < 2; ++ks) {
            uint32_t bf[4][2];
            const int brow = wn * 32 + (lane & 7) + ((lane >> 4) << 3);
            const int bcol = ks * 16 + (lane & 8);
#pragma unroll
            for (int ntp = 0; ntp < 2; ++ntp) {
                uint32_t rr[4];
                ldsm_x4(rr, stg(cur) + S1_OFF_B + swz32(brow + ntp * 16, bcol));
                bf[2 * ntp][0] = rr[0]; bf[2 * ntp][1] = rr[1];
                bf[2 * ntp + 1][0] = rr[2]; bf[2 * ntp + 1][1] = rr[3];
            }
            const int arow = wm * 64 + (lane & 15);
            const int acol = ks * 16 + ((lane >> 4) << 3);
#pragma unroll
            for (int mt = 0; mt < 4; ++mt) {
                uint32_t af[4];
                ldsm_x4(af, stg(cur) + swz32(arow + mt * 16, acol));
#pragma unroll
                for (int nt = 0; nt < 4; ++nt) mma_f16(acc[mt][nt], af, bf[nt]);
            }
        }

        if (kt + 2 < 8) {
            stsA(stg(nx));                       // register-heavy work after MMAs
            if (kt + 3 < 8) loadA(kt + 3);
        }
        if (++cur == 3) cur = 0;
    }

    // epilogue: scatter y into per-p layout [t, s*32+l], fp16
#pragma unroll
    for (int mt = 0; mt < 4; ++mt) {
#pragma unroll
        for (int nt = 0; nt < 4; ++nt) {
            int j = wn * 32 + nt * 8 + ((lane & 3) << 1);
            int p = j >> 5, l = j & 31;
#pragma unroll
            for (int half = 0; half < 2; ++half) {
                int a  = wm * 64 + mt * 16 + (lane >> 2) + half * 8;
                int mg = m0 + a;
                int t = mg >> 4, s = mg & 15;
                size_t off = (size_t)p * YPITCH + (size_t)t * K2 + s * 32 + l;
                *reinterpret_cast<__half2*>(g_y + off) =
                    __halves2half2(__float2half_rn(acc[mt][nt][2 * half]),
                                   __float2half_rn(acc[mt][nt][2 * half + 1]));
            }
        }
    }
}

// ---------------------------------------------------------------------------
// Stage 2: out[t, p*1024+r] = Y_p(8192x512) @ V_p^T(512x1024) + aux.
// CTA tile 128(M) x 128(N), 256 threads, warp tile 32x64, K-slab 64,
// 3-stage 32KB pipeline, 2 CTAs/SM. (R14 version, measured best.)
// ---------------------------------------------------------------------------
#define S2_OFF_B 16384                      // A 128x64 = 16KB, B 128x64 = 16KB
#define S2_STAGE 32768
#define S2_DYN   (3 * S2_STAGE + 128)

__global__ __launch_bounds__(256, 2)
void gemm2(const float* __restrict__ bias, const float* __restrict__ d_mean,
           const float* __restrict__ d_std, float* __restrict__ out) {
    extern __shared__ __half smraw[];
    const uint32_t sdata = ((uint32_t)__cvta_generic_to_shared(smraw) + 127u) & ~127u;

    const int tid  = threadIdx.x;
    const int lane = tid & 31;
    const int warp = tid >> 5;        // 0..7
    const int wm   = warp >> 1;       // 0..3, 32-row slice
    const int wn   = warp & 1;        // 0..1, 64-col slice
    const int bn   = blockIdx.x;      // 0..7  (128-col tile within p)
    const int bm   = blockIdx.y;      // 0..63 (128-token tile)
    const int p    = blockIdx.z;      // 0..3

    const __half* gx = g_y + (size_t)p * YPITCH + (size_t)bm * 128 * K2;
    const __half* gw = g_v + (size_t)p * VPITCH + (size_t)bn * 128 * K2;

    int rr_[4], cc_[4]; uint32_t dd_[4];
#pragma unroll
    for (int e = 0; e < 4; ++e) {
        int u = tid + e * 256;
        rr_[e] = u >> 3; cc_[e] = (u & 7) << 3;
        dd_[e] = swz64(rr_[e], cc_[e]);
    }

    auto load_tile = [&](uint32_t st, int k0) {
#pragma unroll
        for (int e = 0; e < 4; ++e)
            cp16(st + dd_[e], gx + (size_t)rr_[e] * K2 + k0 + cc_[e]);
#pragma unroll
        for (int e = 0; e < 4; ++e)
            cp16(st + S2_OFF_B + dd_[e], gw + (size_t)rr_[e] * K2 + k0 + cc_[e]);
        cp_commit();
    };
    auto stg = [&](int s) -> uint32_t { return sdata + (uint32_t)s * S2_STAGE; };

    float acc[2][8][4] = {};

    load_tile(stg(0), 0);
    load_tile(stg(1), 64);

    const int brow = wn * 64 + (lane & 7) + ((lane >> 4) << 3);
    const int arow = wm * 32 + (lane & 15);

    int cur = 0;
    for (int kt = 0; kt < 8; ++kt) {
        if (kt < 7) cp_wait1(); else cp_wait0();
        __syncthreads();
        if (kt + 2 < 8) {
            int nx = cur + 2; if (nx >= 3) nx -= 3;
            load_tile(stg(nx), (kt + 2) * 64);
        }

        const uint32_t st = stg(cur);
#pragma unroll
        for (int ks = 0; ks < 4; ++ks) {
            uint32_t bf[8][2];
            const int bcol = ks * 16 + (lane & 8);
#pragma unroll
            for (int ntp = 0; ntp < 4; ++ntp) {
                uint32_t rr[4];
                ldsm_x4(rr, st + S2_OFF_B + swz64(brow + ntp * 16, bcol));
                bf[2 * ntp][0] = rr[0]; bf[2 * ntp][1] = rr[1];
                bf[2 * ntp + 1][0] = rr[2]; bf[2 * ntp + 1][1] = rr[3];
            }
            const int acol = ks * 16 + ((lane >> 4) << 3);
#pragma unroll
            for (int mt = 0; mt < 2; ++mt) {
                uint32_t af[4];
                ldsm_x4(af, st + swz64(arow + mt * 16, acol));
#pragma unroll
                for (int nt = 0; nt < 8; ++nt) mma_f16(acc[mt][nt], af, bf[nt]);
            }
        }
        if (++cur == 3) cur = 0;
    }

    const float mean = d_mean[p];
    const float stdp = d_std[p] + 1e-6f;

#pragma unroll
    for (int mt = 0; mt < 2; ++mt) {
        int t0 = bm * 128 + wm * 32 + mt * 16 + (lane >> 2);
        float base0 = mean * g_xs[t0]     + stdp * g_xb[t0 * 4 + p];
        float base1 = mean * g_xs[t0 + 8] + stdp * g_xb[(t0 + 8) * 4 + p];
#pragma unroll
        for (int nt = 0; nt < 8; ++nt) {
            int o = p * 1024 + bn * 128 + wn * 64 + nt * 8 + ((lane & 3) << 1);
            float b0 = bias[o], b1 = bias[o + 1];
            float2* p0 = reinterpret_cast<float2*>(out + (size_t)t0 * OUT_F + o);
            float2* p1 = reinterpret_cast<float2*>(out + (size_t)(t0 + 8) * OUT_F + o);
            *p0 = make_float2(acc[mt][nt][0] + b0 + base0, acc[mt][nt][1] + b1 + base0);
            *p1 = make_float2(acc[mt][nt][2] + b0 + base1, acc[mt][nt][3] + b1 + base1);
        }
    }
}

// ---------------------------------------------------------------------------
extern "C" void kernel_launch(void* const* d_in, const int* in_sizes, int n_in,
                              void* d_out, int out_size) {
    (void)in_sizes; (void)n_in; (void)out_size;
    const float* x      = (const float*)d_in[0];
    const float* vq     = (const float*)d_in[1];
    const float* w_dec  = (const float*)d_in[2];
    const float* b_dec  = (const float*)d_in[3];
    const float* d_mean = (const float*)d_in[4];
    const float* d_std  = (const float*)d_in[5];
    const float* bias   = (const float*)d_in[6];
    float* out = (float*)d_out;

    prep_wd<<<128, 256>>>(w_dec);

    cudaFuncSetAttribute(y_gemm_fused, cudaFuncAttributeMaxDynamicSharedMemorySize, S1_DYN);
    y_gemm_fused<<<17408, 256, S1_DYN>>>(x, vq, d_std, b_dec);

    cudaFuncSetAttribute(gemm2, cudaFuncAttributeMaxDynamicSharedMemorySize, S2_DYN);
    gemm2<<<dim3(8, 64, 4), 256, S2_DYN>>>(bias, d_mean, d_std, out);
}

// round 17
// speedup vs baseline: 1.1951x; 1.1951x over previous
#include <cuda_runtime.h>
#include <cuda_fp16.h>
#include <cstdint>

#define IN_F   4096
#define OUT_F  4096
#define M_TOK  8192
#define XK     256                      // stage-1 contraction (x_flat cols)
#define K2     512                      // stage-2 contraction = 16*32
#define YPITCH ((size_t)M_TOK * K2)     // per-p Y matrix elems
#define VPITCH ((size_t)1024 * K2)      // per-p V matrix elems

// Scratch (allocation-free rule: __device__ globals).
__device__ __align__(256) __half g_wd[128 * 256];
__device__ __align__(256) __half g_y[4 * YPITCH];
__device__ __align__(256) __half g_v[4 * VPITCH];
__device__ float g_xs[M_TOK];
__device__ float g_xb[M_TOK * 4];

// ---------------------------------------------------------------------------
// helpers
// ---------------------------------------------------------------------------
__device__ __forceinline__ void mma_f16(float* c, const uint32_t* a, const uint32_t* b) {
    asm volatile(
        "mma.sync.aligned.m16n8k16.row.col.f32.f16.f16.f32 "
        "{%0,%1,%2,%3}, {%4,%5,%6,%7}, {%8,%9}, {%0,%1,%2,%3};\n"
        : "+f"(c[0]), "+f"(c[1]), "+f"(c[2]), "+f"(c[3])
        : "r"(a[0]), "r"(a[1]), "r"(a[2]), "r"(a[3]), "r"(b[0]), "r"(b[1]));
}
__device__ __forceinline__ void ldsm_x4(uint32_t* r, uint32_t addr) {
    asm volatile("ldmatrix.sync.aligned.m8n8.x4.shared.b16 {%0,%1,%2,%3}, [%4];\n"
                 : "=r"(r[0]), "=r"(r[1]), "=r"(r[2]), "=r"(r[3]) : "r"(addr));
}
__device__ __forceinline__ void cp16(uint32_t saddr, const void* g) {
    asm volatile("cp.async.cg.shared.global [%0], [%1], 16;\n" :: "r"(saddr), "l"(g) : "memory");
}
__device__ __forceinline__ void cp_commit() { asm volatile("cp.async.commit_group;\n" ::: "memory"); }
__device__ __forceinline__ void cp_wait1()  { asm volatile("cp.async.wait_group 1;\n" ::: "memory"); }
__device__ __forceinline__ void cp_wait0()  { asm volatile("cp.async.wait_group 0;\n" ::: "memory"); }

// swizzle for 32-col tiles: 2 rows per 128B line. r:0..127, c:0..31 (fp16)
__device__ __forceinline__ uint32_t swz32(int r, int c) {
    int line = r >> 1;
    int q = ((r & 1) << 2) | (c >> 3);
    return (uint32_t)((line << 7) | ((q ^ (line & 7)) << 4) | ((c & 7) << 1));
}
// swizzle for 64-col tiles: 1 row per 128B line. r: any, c:0..63 (fp16)
__device__ __forceinline__ uint32_t swz64(int r, int c) {
    int q = c >> 3;
    return (uint32_t)((r << 7) | (((q ^ (r & 7)) & 7) << 4) | ((c & 7) << 1));
}

// ---------------------------------------------------------------------------
// prep: [0,128): wd split; [128,8320): V build.  (aux deleted — now in y_gemm)
// ---------------------------------------------------------------------------
__global__ void prep_all(const float* __restrict__ w_dec,
                         const float* __restrict__ vq,
                         const float* __restrict__ d_std) {
    if (blockIdx.x < 128) {
        int i = blockIdx.x * 256 + threadIdx.x;        // < 32768
        g_wd[i] = __float2half_rn(w_dec[i]);
    } else {
        int i = (blockIdx.x - 128) * 256 + threadIdx.x; // < 2097152
        int n = i >> 7, low = i & 127;
        int p = low >> 5, l = low & 31;
        int r = n >> 4, s = n & 15;
        float v = vq[i] * (d_std[p] + 1e-6f);
        g_v[(size_t)p * VPITCH + (size_t)r * K2 + s * 32 + l] = __float2half_rn(v);
    }
}

// ---------------------------------------------------------------------------
// Stage 1: y = x_flat(131072x256) @ wd^T(256x128), fp16 mma, K-slab 32,
// 3-stage pipeline + FUSED aux (xb/xs) via extra n8 MMA on wn==0 warps.
// baux (8 x 256): rows 0..3 = b_dec[p][c], row 4 = ones, rows 5..7 = 0.
// ---------------------------------------------------------------------------
#define S1_OFF_B 8192
#define S1_STAGE 16384
#define S1_OFF_AUX (3 * S1_STAGE)          // baux_T: 8 rows x 264 halves = 4224B
#define S1_DYN   (S1_OFF_AUX + 4224 + 128)
#define AUX_STRIDE 528                     // bytes per baux row (264 halves)

__global__ __launch_bounds__(256, 2)
void y_gemm(const float* __restrict__ x, const float* __restrict__ b_dec) {
    extern __shared__ __half smraw[];
    const uint32_t sdata = ((uint32_t)__cvta_generic_to_shared(smraw) + 127u) & ~127u;
    const uint32_t sbaux = sdata + S1_OFF_AUX;

    const int tid  = threadIdx.x;
    const int lane = tid & 31;
    const int warp = tid >> 5;
    const int wm   = warp >> 2;
    const int wn   = warp & 3;
    const int m0   = blockIdx.x * 128;

    // init baux_T[n][k]: n 0..3 = b_dec, 4 = ones, 5..7 = 0
#pragma unroll
    for (int n = 0; n < 8; ++n) {
        __half v = (n < 4) ? __float2half_rn(b_dec[n * 256 + tid])
                           : ((n == 4) ? __float2half_rn(1.0f) : __float2half_rn(0.0f));
        asm volatile("st.shared.b16 [%0], %1;" :: "r"(sbaux + n * AUX_STRIDE + tid * 2),
                     "h"(*reinterpret_cast<uint16_t*>(&v)) : "memory");
    }

    const int u0 = tid, u1 = tid + 256;
    const int r0 = u0 >> 2, c0 = (u0 & 3) << 3;
    const int r1 = u1 >> 2, c1 = (u1 & 3) << 3;
    const uint32_t d0 = swz32(r0, c0), d1 = swz32(r1, c1);

    float acc[4][4][4] = {};
    float accaux[4][4] = {};
    float4 ra[2][2];

    auto loadA = [&](int kt) {
        const float4* p0 = reinterpret_cast<const float4*>(x + (size_t)(m0 + r0) * XK + kt * 32 + c0);
        const float4* p1 = reinterpret_cast<const float4*>(x + (size_t)(m0 + r1) * XK + kt * 32 + c1);
        ra[0][0] = p0[0]; ra[0][1] = p0[1];
        ra[1][0] = p1[0]; ra[1][1] = p1[1];
    };
    auto stsA = [&](uint32_t st) {
#pragma unroll
        for (int e = 0; e < 2; ++e) {
            const float* f = reinterpret_cast<const float*>(ra[e]);
            __half2 hv[4];
#pragma unroll
            for (int j = 0; j < 4; ++j)
                hv[j] = __halves2half2(__float2half_rn(f[2 * j]), __float2half_rn(f[2 * j + 1]));
            asm volatile("st.shared.v4.b32 [%0], {%1,%2,%3,%4};\n" ::
                "r"(st + (e ? d1 : d0)),
                "r"(*reinterpret_cast<uint32_t*>(&hv[0])), "r"(*reinterpret_cast<uint32_t*>(&hv[1])),
                "r"(*reinterpret_cast<uint32_t*>(&hv[2])), "r"(*reinterpret_cast<uint32_t*>(&hv[3])));
        }
    };
    auto cpB = [&](uint32_t st, int kt) {
        cp16(st + S1_OFF_B + d0, g_wd + r0 * 256 + kt * 32 + c0);
        cp16(st + S1_OFF_B + d1, g_wd + r1 * 256 + kt * 32 + c1);
        cp_commit();
    };
    auto stg = [&](int s) -> uint32_t { return sdata + (uint32_t)s * S1_STAGE; };

    // per-thread baux fragment base: row n=lane>>2, k offset (lane&3)*2
    const uint32_t auxbase = sbaux + (uint32_t)(lane >> 2) * AUX_STRIDE + (uint32_t)(lane & 3) * 4;

    // prologue
    loadA(0); stsA(stg(0)); cpB(stg(0), 0);
    loadA(1); stsA(stg(1)); cpB(stg(1), 1);
    loadA(2);

    int cur = 0;
    for (int kt = 0; kt < 8; ++kt) {
        if (kt < 7) cp_wait1(); else cp_wait0();
        __syncthreads();
        int nx = cur + 2; if (nx >= 3) nx -= 3;
        if (kt + 2 < 8) cpB(stg(nx), kt + 2);   // cheap prefetch before MMAs

#pragma unroll
        for (int ks = 0; ks < 2; ++ks) {
            uint32_t bf[4][2];
            const int brow = wn * 32 + (lane & 7) + ((lane >> 4) << 3);
            const int bcol = ks * 16 + (lane & 8);
#pragma unroll
            for (int ntp = 0; ntp < 2; ++ntp) {
                uint32_t rr[4];
                ldsm_x4(rr, stg(cur) + S1_OFF_B + swz32(brow + ntp * 16, bcol));
                bf[2 * ntp][0] = rr[0]; bf[2 * ntp][1] = rr[1];
                bf[2 * ntp + 1][0] = rr[2]; bf[2 * ntp + 1][1] = rr[3];
            }
            // baux fragment for this k16 (wn==0 warps only)
            uint32_t bb[2];
            if (wn == 0) {
                const uint32_t ka = auxbase + (uint32_t)(kt * 32 + ks * 16) * 2;
                asm volatile("ld.shared.b32 %0, [%1];" : "=r"(bb[0]) : "r"(ka));
                asm volatile("ld.shared.b32 %0, [%1];" : "=r"(bb[1]) : "r"(ka + 16));
            }
            const int arow = wm * 64 + (lane & 15);
            const int acol = ks * 16 + ((lane >> 4) << 3);
#pragma unroll
            for (int mt = 0; mt < 4; ++mt) {
                uint32_t af[4];
                ldsm_x4(af, stg(cur) + swz32(arow + mt * 16, acol));
#pragma unroll
                for (int nt = 0; nt < 4; ++nt) mma_f16(acc[mt][nt], af, bf[nt]);
                if (wn == 0) mma_f16(accaux[mt], af, bb);
            }
        }

        if (kt + 2 < 8) {
            stsA(stg(nx));                       // register-heavy work after MMAs
            if (kt + 3 < 8) loadA(kt + 3);
        }
        if (++cur == 3) cur = 0;
    }

    // ------- aux reduction + write (wn==0 warps) -------
    if (wn == 0) {
#pragma unroll
        for (int mt = 0; mt < 4; ++mt) {
            float cA = accaux[mt][0] + accaux[mt][2];   // even col of pair
            float cB = accaux[mt][1] + accaux[mt][3];   // odd col
#pragma unroll
            for (int o = 4; o <= 16; o <<= 1) {
                cA += __shfl_xor_sync(0xffffffffu, cA, o);
                cB += __shfl_xor_sync(0xffffffffu, cB, o);
            }
            int t = blockIdx.x * 8 + wm * 4 + mt;
            if (lane == 0)      { g_xb[t * 4 + 0] = cA; g_xb[t * 4 + 1] = cB; }
            else if (lane == 1) { g_xb[t * 4 + 2] = cA; g_xb[t * 4 + 3] = cB; }
            else if (lane == 2) { g_xs[t] = cA; }
        }
    }

    // epilogue: scatter y into per-p layout [t, s*32+l], fp16
#pragma unroll
    for (int mt = 0; mt < 4; ++mt) {
#pragma unroll
        for (int nt = 0; nt < 4; ++nt) {
            int j = wn * 32 + nt * 8 + ((lane & 3) << 1);
            int p = j >> 5, l = j & 31;
#pragma unroll
            for (int half = 0; half < 2; ++half) {
                int a  = wm * 64 + mt * 16 + (lane >> 2) + half * 8;
                int mg = m0 + a;
                int t = mg >> 4, s = mg & 15;
                size_t off = (size_t)p * YPITCH + (size_t)t * K2 + s * 32 + l;
                *reinterpret_cast<__half2*>(g_y + off) =
                    __halves2half2(__float2half_rn(acc[mt][nt][2 * half]),
                                   __float2half_rn(acc[mt][nt][2 * half + 1]));
            }
        }
    }
}

// ---------------------------------------------------------------------------
// Stage 2: out[t, p*1024+r] = Y_p(8192x512) @ V_p^T(512x1024) + aux.
// CTA tile 128(M) x 128(N), 256 threads, warp tile 32x64, K-slab 64,
// 3-stage 32KB pipeline, 2 CTAs/SM. (R14 version, measured best 102.6us.)
// ---------------------------------------------------------------------------
#define S2_OFF_B 16384                      // A 128x64 = 16KB, B 128x64 = 16KB
#define S2_STAGE 32768
#define S2_DYN   (3 * S2_STAGE + 128)

__global__ __launch_bounds__(256, 2)
void gemm2(const float* __restrict__ bias, const float* __restrict__ d_mean,
           const float* __restrict__ d_std, float* __restrict__ out) {
    extern __shared__ __half smraw[];
    const uint32_t sdata = ((uint32_t)__cvta_generic_to_shared(smraw) + 127u) & ~127u;

    const int tid  = threadIdx.x;
    const int lane = tid & 31;
    const int warp = tid >> 5;        // 0..7
    const int wm   = warp >> 1;       // 0..3, 32-row slice
    const int wn   = warp & 1;        // 0..1, 64-col slice
    const int bn   = blockIdx.x;      // 0..7  (128-col tile within p)
    const int bm   = blockIdx.y;      // 0..63 (128-token tile)
    const int p    = blockIdx.z;      // 0..3

    const __half* gx = g_y + (size_t)p * YPITCH + (size_t)bm * 128 * K2;
    const __half* gw = g_v + (size_t)p * VPITCH + (size_t)bn * 128 * K2;

    int rr_[4], cc_[4]; uint32_t dd_[4];
#pragma unroll
    for (int e = 0; e < 4; ++e) {
        int u = tid + e * 256;
        rr_[e] = u >> 3; cc_[e] = (u & 7) << 3;
        dd_[e] = swz64(rr_[e], cc_[e]);
    }

    auto load_tile = [&](uint32_t st, int k0) {
#pragma unroll
        for (int e = 0; e < 4; ++e)
            cp16(st + dd_[e], gx + (size_t)rr_[e] * K2 + k0 + cc_[e]);
#pragma unroll
        for (int e = 0; e < 4; ++e)
            cp16(st + S2_OFF_B + dd_[e], gw + (size_t)rr_[e] * K2 + k0 + cc_[e]);
        cp_commit();
    };
    auto stg = [&](int s) -> uint32_t { return sdata + (uint32_t)s * S2_STAGE; };

    float acc[2][8][4] = {};

    load_tile(stg(0), 0);
    load_tile(stg(1), 64);

    const int brow = wn * 64 + (lane & 7) + ((lane >> 4) << 3);
    const int arow = wm * 32 + (lane & 15);

    int cur = 0;
    for (int kt = 0; kt < 8; ++kt) {
        if (kt < 7) cp_wait1(); else cp_wait0();
        __syncthreads();
        if (kt + 2 < 8) {
            int nx = cur + 2; if (nx >= 3) nx -= 3;
            load_tile(stg(nx), (kt + 2) * 64);
        }

        const uint32_t st = stg(cur);
#pragma unroll
        for (int ks = 0; ks < 4; ++ks) {
            uint32_t bf[8][2];
            const int bcol = ks * 16 + (lane & 8);
#pragma unroll
            for (int ntp = 0; ntp < 4; ++ntp) {
                uint32_t rr[4];
                ldsm_x4(rr, st + S2_OFF_B + swz64(brow + ntp * 16, bcol));
                bf[2 * ntp][0] = rr[0]; bf[2 * ntp][1] = rr[1];
                bf[2 * ntp + 1][0] = rr[2]; bf[2 * ntp + 1][1] = rr[3];
            }
            const int acol = ks * 16 + ((lane >> 4) << 3);
#pragma unroll
            for (int mt = 0; mt < 2; ++mt) {
                uint32_t af[4];
                ldsm_x4(af, st + swz64(arow + mt * 16, acol));
#pragma unroll
                for (int nt = 0; nt < 8; ++nt) mma_f16(acc[mt][nt], af, bf[nt]);
            }
        }
        if (++cur == 3) cur = 0;
    }

    const float mean = d_mean[p];
    const float stdp = d_std[p] + 1e-6f;

#pragma unroll
    for (int mt = 0; mt < 2; ++mt) {
        int t0 = bm * 128 + wm * 32 + mt * 16 + (lane >> 2);
        float base0 = mean * g_xs[t0]     + stdp * g_xb[t0 * 4 + p];
        float base1 = mean * g_xs[t0 + 8] + stdp * g_xb[(t0 + 8) * 4 + p];
#pragma unroll
        for (int nt = 0; nt < 8; ++nt) {
            int o = p * 1024 + bn * 128 + wn * 64 + nt * 8 + ((lane & 3) << 1);
            float b0 = bias[o], b1 = bias[o + 1];
            float2* p0 = reinterpret_cast<float2*>(out + (size_t)t0 * OUT_F + o);
            float2* p1 = reinterpret_cast<float2*>(out + (size_t)(t0 + 8) * OUT_F + o);
            *p0 = make_float2(acc[mt][nt][0] + b0 + base0, acc[mt][nt][1] + b1 + base0);
            *p1 = make_float2(acc[mt][nt][2] + b0 + base1, acc[mt][nt][3] + b1 + base1);
        }
    }
}

// ---------------------------------------------------------------------------
extern "C" void kernel_launch(void* const* d_in, const int* in_sizes, int n_in,
                              void* d_out, int out_size) {
    (void)in_sizes; (void)n_in; (void)out_size;
    const float* x      = (const float*)d_in[0];
    const float* vq     = (const float*)d_in[1];
    const float* w_dec  = (const float*)d_in[2];
    const float* b_dec  = (const float*)d_in[3];
    const float* d_mean = (const float*)d_in[4];
    const float* d_std  = (const float*)d_in[5];
    const float* bias   = (const float*)d_in[6];
    float* out = (float*)d_out;

    prep_all<<<8320, 256>>>(w_dec, vq, d_std);

    cudaFuncSetAttribute(y_gemm, cudaFuncAttributeMaxDynamicSharedMemorySize, S1_DYN);
    y_gemm<<<1024, 256, S1_DYN>>>(x, b_dec);

    cudaFuncSetAttribute(gemm2, cudaFuncAttributeMaxDynamicSharedMemorySize, S2_DYN);
    gemm2<<<dim3(8, 64, 4), 256, S2_DYN>>>(bias, d_mean, d_std, out);
}